// round 1
// baseline (speedup 1.0000x reference)
#include <cuda_runtime.h>
#include <cuda_bf16.h>
#include <cstdint>

#define DEPTH_DIM 256
// Scratch in [H*W, D] layout so each point's 256-float row is contiguous (coalesced REDs).
// 256*704*256 floats = 46,137,344 * 4B = ~184.5 MB static device scratch (alloc-free rule).
#define SCRATCH_ELEMS (256 * 704 * 256)
__device__ float g_scratch[SCRATCH_ELEMS];

// ---------------------------------------------------------------------------
// Kernel 1: zero the scratch (float4 grid-stride)
// ---------------------------------------------------------------------------
__global__ void zero_scratch_kernel(int n4) {
    float4* p = reinterpret_cast<float4*>(g_scratch);
    const float4 z = make_float4(0.f, 0.f, 0.f, 0.f);
    int i = blockIdx.x * blockDim.x + threadIdx.x;
    int stride = gridDim.x * blockDim.x;
    for (; i < n4; i += stride) p[i] = z;
}

// ---------------------------------------------------------------------------
// Vectorized reduction (sm_90+): 16B of payload per lane-op, 4x fewer RED ops.
// Address is 16B aligned: lin*1024 + lane*32 bytes into a static array.
// ---------------------------------------------------------------------------
__device__ __forceinline__ void red_add_v4(float* addr, float a, float b, float c, float d) {
    asm volatile("red.global.add.v4.f32 [%0], {%1, %2, %3, %4};"
                 :: "l"(addr), "f"(a), "f"(b), "f"(c), "f"(d)
                 : "memory");
}

// ---------------------------------------------------------------------------
// Kernel 2: one warp per point.
//   d_coors window: x[d] = h * k,  k = d - depth - (d > depth),  h = 6/255.
//   probs normalized by L2 norm, so the 1/(sigma*sqrt(2pi)) factor cancels:
//   we only need g[d] = exp(-0.5 * (h*k/sigma)^2) and its L2 norm.
//   Lane L owns d = 8L..8L+7 -> warp covers the full contiguous 1KB row.
// ---------------------------------------------------------------------------
__global__ void scatter_kernel(const int2* __restrict__ pos,
                               const int*  __restrict__ depth,
                               const float* __restrict__ conf,
                               const int*  __restrict__ pW,
                               int npts) {
    int warp = (blockIdx.x * blockDim.x + threadIdx.x) >> 5;
    int lane = threadIdx.x & 31;
    if (warp >= npts) return;

    int W = pW ? __ldg(pW) : 704;

    int2  uv    = __ldg(&pos[warp]);
    int   p     = __ldg(&depth[warp]);
    float sigma = __ldg(&conf[warp]);

    const float h = 6.0f / 255.0f;
    float na = -0.5f * h * h / (sigma * sigma);   // -a, so g = exp(na * k^2)

    int dbase = lane * 8;
    float vals[8];
    float s = 0.0f;
#pragma unroll
    for (int j = 0; j < 8; ++j) {
        int d = dbase + j;
        int k = d - p - (d > p);                  // duplicate k=0 at d=p, d=p+1 (matches ref)
        float kf = (float)k;
        float g = __expf(na * kf * kf);
        vals[j] = g;
        s = fmaf(g, g, s);
    }
    // warp-reduce sum of squares
#pragma unroll
    for (int o = 16; o > 0; o >>= 1)
        s += __shfl_xor_sync(0xffffffffu, s, o);

    // s >= 1 always (the k=0 term is exp(0)=1), so no eps clamp needed
    float inv = rsqrtf(s);

    long long lin = (long long)uv.y * W + uv.x;
    float* base = g_scratch + lin * DEPTH_DIM + dbase;
    red_add_v4(base,     vals[0]*inv, vals[1]*inv, vals[2]*inv, vals[3]*inv);
    red_add_v4(base + 4, vals[4]*inv, vals[5]*inv, vals[6]*inv, vals[7]*inv);
}

// ---------------------------------------------------------------------------
// Kernel 3: transpose scratch [HW, 256] -> out [256, HW]  (32x32 smem tiles)
// ---------------------------------------------------------------------------
__global__ void transpose_kernel(float* __restrict__ out, int HW) {
    __shared__ float tile[32][33];
    int pBlock = blockIdx.x * 32;   // position tile
    int dBlock = blockIdx.y * 32;   // depth tile (256/32 = 8)
    int tx = threadIdx.x;           // 0..31
    int ty = threadIdx.y;           // 0..7

    // read coalesced along d
#pragma unroll
    for (int r = 0; r < 32; r += 8) {
        int pp = pBlock + ty + r;
        if (pp < HW)
            tile[ty + r][tx] = g_scratch[(long long)pp * DEPTH_DIM + dBlock + tx];
    }
    __syncthreads();

    // write coalesced along p
#pragma unroll
    for (int r = 0; r < 32; r += 8) {
        int dd = dBlock + ty + r;
        int pp = pBlock + tx;
        if (pp < HW)
            out[(long long)dd * HW + pp] = tile[tx][ty + r];
    }
}

// ---------------------------------------------------------------------------
// Launch
// ---------------------------------------------------------------------------
extern "C" void kernel_launch(void* const* d_in, const int* in_sizes, int n_in,
                              void* d_out, int out_size) {
    const int2*  pos   = (const int2*)d_in[0];   // [N,2] int32 (u=x, v=y)
    const int*   depth = (const int*)d_in[1];    // [N,1] int32
    const float* conf  = (const float*)d_in[2];  // [N,1] float32
    const int*   pW    = (n_in >= 5) ? (const int*)d_in[4] : nullptr;

    int npts  = in_sizes[1];             // pts_depth element count = N
    int total = out_size;                // D*H*W
    int HW    = total / DEPTH_DIM;

    // 1) zero scratch
    zero_scratch_kernel<<<2048, 256>>>(total / 4);

    // 2) scatter: one warp per point, 8 warps per block
    int blocks = (npts + 7) / 8;
    scatter_kernel<<<blocks, 256>>>(pos, depth, conf, pW, npts);

    // 3) transpose to output layout
    dim3 tb(32, 8);
    dim3 tg((HW + 31) / 32, DEPTH_DIM / 32);
    transpose_kernel<<<tg, tb>>>((float*)d_out, HW);
}

// round 2
// speedup vs baseline: 2.0050x; 2.0050x over previous
#include <cuda_runtime.h>
#include <cuda_bf16.h>
#include <cstdint>

#define DEPTH_DIM 256
#define MAX_HW    (1 << 20)      // up to 1M pixels
#define MAX_N     (1 << 21)      // up to 2M points
#define SCAN_B    256

__device__ int   g_counts[MAX_HW];
__device__ int   g_localOff[MAX_HW];
__device__ int   g_blockSums[MAX_HW / SCAN_B];
__device__ int   g_blockOff[MAX_HW / SCAN_B];
__device__ int   g_rank[MAX_N];
__device__ int   g_binDepth[MAX_N];
__device__ float g_binConf[MAX_N];

// ---------------------------------------------------------------------------
// K1: zero per-pixel counters
// ---------------------------------------------------------------------------
__global__ void zero_counts_kernel(int HW) {
    int i = blockIdx.x * blockDim.x + threadIdx.x;
    int stride = gridDim.x * blockDim.x;
    for (; i < HW; i += stride) g_counts[i] = 0;
}

// ---------------------------------------------------------------------------
// K2: histogram; also record each point's rank within its pixel
// ---------------------------------------------------------------------------
__global__ void hist_kernel(const int2* __restrict__ pos,
                            const int* __restrict__ pW, int npts) {
    int i = blockIdx.x * blockDim.x + threadIdx.x;
    if (i >= npts) return;
    int W = __ldg(pW);
    int2 uv = __ldg(&pos[i]);
    int lin = uv.y * W + uv.x;
    g_rank[i] = atomicAdd(&g_counts[lin], 1);
}

// ---------------------------------------------------------------------------
// K3: per-block exclusive scan of counts (256 elems per block) + block sums
// ---------------------------------------------------------------------------
__global__ void block_scan_kernel(int HW) {
    __shared__ int sm[SCAN_B];
    int tid = threadIdx.x;
    int i = blockIdx.x * SCAN_B + tid;
    int v = (i < HW) ? g_counts[i] : 0;
    sm[tid] = v;
    __syncthreads();
#pragma unroll
    for (int off = 1; off < SCAN_B; off <<= 1) {
        int t = (tid >= off) ? sm[tid - off] : 0;
        __syncthreads();
        if (tid >= off) sm[tid] += t;
        __syncthreads();
    }
    if (i < HW) g_localOff[i] = sm[tid] - v;          // exclusive
    if (tid == SCAN_B - 1) g_blockSums[blockIdx.x] = sm[tid];
}

// ---------------------------------------------------------------------------
// K4: single-block chunked exclusive scan of block sums (nB <= 4096)
// ---------------------------------------------------------------------------
__global__ void scan_blocksums_kernel(int nB) {
    __shared__ int sm[1024];
    __shared__ int carry_s;
    int tid = threadIdx.x;
    if (tid == 0) carry_s = 0;
    __syncthreads();
    for (int base = 0; base < nB; base += 1024) {
        int i = base + tid;
        int v = (i < nB) ? g_blockSums[i] : 0;
        sm[tid] = v;
        __syncthreads();
#pragma unroll
        for (int off = 1; off < 1024; off <<= 1) {
            int t = (tid >= off) ? sm[tid - off] : 0;
            __syncthreads();
            if (tid >= off) sm[tid] += t;
            __syncthreads();
        }
        int carry = carry_s;
        if (i < nB) g_blockOff[i] = carry + sm[tid] - v;  // exclusive
        int tot = sm[1023];
        __syncthreads();
        if (tid == 0) carry_s = carry + tot;
        __syncthreads();
    }
}

// ---------------------------------------------------------------------------
// K5: scatter point payloads (depth, conf) into their bin slots
// ---------------------------------------------------------------------------
__global__ void bin_scatter_kernel(const int2* __restrict__ pos,
                                   const int* __restrict__ depth,
                                   const float* __restrict__ conf,
                                   const int* __restrict__ pW, int npts) {
    int i = blockIdx.x * blockDim.x + threadIdx.x;
    if (i >= npts) return;
    int W = __ldg(pW);
    int2 uv = __ldg(&pos[i]);
    int lin = uv.y * W + uv.x;
    int slot = g_localOff[lin] + g_blockOff[lin >> 8] + g_rank[i];
    g_binDepth[slot] = __ldg(&depth[i]);
    g_binConf[slot]  = __ldg(&conf[i]);
}

// ---------------------------------------------------------------------------
// K6: fused accumulate + transposed write.
//   Block = 32 consecutive pixels x 256 depths. 8 warps; warp w owns pixels
//   4w..4w+3. Lane L owns depths d = L + 32m (m=0..7) so the smem stores and
//   output reads are bank-conflict-free with a 33-stride tile.
//   No smem zeroing: register accumulators start at 0 and every (d, j) cell
//   is written exactly once.
// ---------------------------------------------------------------------------
__global__ void fused_kernel(float* __restrict__ out, int HW) {
    __shared__ float tile[DEPTH_DIM][33];
    int warp = threadIdx.x >> 5;
    int lane = threadIdx.x & 31;
    int pBase = blockIdx.x * 32;

    const float h = 6.0f / 255.0f;

#pragma unroll
    for (int jj = 0; jj < 4; ++jj) {
        int j = warp * 4 + jj;
        int p = pBase + j;
        float acc[8] = {0.f, 0.f, 0.f, 0.f, 0.f, 0.f, 0.f, 0.f};
        if (p < HW) {
            int off = g_localOff[p] + g_blockOff[p >> 8];
            int cnt = g_counts[p];
            for (int t = 0; t < cnt; ++t) {
                int   pd    = g_binDepth[off + t];
                float sigma = g_binConf[off + t];
                float na = -0.5f * h * h / (sigma * sigma);
                float g[8];
                float s = 0.f;
#pragma unroll
                for (int m = 0; m < 8; ++m) {
                    int d = lane + 32 * m;
                    int k = d - pd - (d > pd);   // window k (duplicate 0 at d=pd,pd+1)
                    float kf = (float)k;
                    g[m] = __expf(na * kf * kf);
                    s = fmaf(g[m], g[m], s);
                }
#pragma unroll
                for (int o = 16; o > 0; o >>= 1)
                    s += __shfl_xor_sync(0xffffffffu, s, o);
                float inv = rsqrtf(s);           // s >= 1 (k=0 term), no eps
#pragma unroll
                for (int m = 0; m < 8; ++m)
                    acc[m] = fmaf(g[m], inv, acc[m]);
            }
        }
#pragma unroll
        for (int m = 0; m < 8; ++m)
            tile[lane + 32 * m][j] = acc[m];     // bank = (lane + j) % 32, conflict-free
    }
    __syncthreads();

    // coalesced write: each warp writes 32 consecutive pixels at one depth
    int tx = threadIdx.x & 31;
    int dBase = threadIdx.x >> 5;   // 0..7
    int p = pBase + tx;
    if (p < HW) {
#pragma unroll
        for (int m = 0; m < 32; ++m) {
            int d = dBase + m * 8;
            out[(size_t)d * HW + p] = tile[d][tx];
        }
    }
}

// ---------------------------------------------------------------------------
// Launch
// ---------------------------------------------------------------------------
extern "C" void kernel_launch(void* const* d_in, const int* in_sizes, int n_in,
                              void* d_out, int out_size) {
    const int2*  pos   = (const int2*)d_in[0];   // [N,2] int32 (u=x, v=y)
    const int*   depth = (const int*)d_in[1];    // [N,1] int32
    const float* conf  = (const float*)d_in[2];  // [N,1] float32
    const int*   pW    = (const int*)d_in[4];    // feat_w scalar

    int npts = in_sizes[1];
    int HW   = out_size / DEPTH_DIM;
    int nB   = (HW + SCAN_B - 1) / SCAN_B;

    zero_counts_kernel<<<512, 256>>>(HW);
    hist_kernel<<<(npts + 255) / 256, 256>>>(pos, pW, npts);
    block_scan_kernel<<<nB, SCAN_B>>>(HW);
    scan_blocksums_kernel<<<1, 1024>>>(nB);
    bin_scatter_kernel<<<(npts + 255) / 256, 256>>>(pos, depth, conf, pW, npts);
    fused_kernel<<<(HW + 31) / 32, 256>>>((float*)d_out, HW);
}